// round 4
// baseline (speedup 1.0000x reference)
#include <cuda_runtime.h>
#include <cstdint>

// Problem constants (fixed by reference)
#define M_CAND    50000
#define K_DIM     2304
#define N_HID     1000
#define NUM_WORDS 5000
#define NTOP      2000
#define MAXW      10
#define SORT_N    65536
#define NTILES    8        // ceil(N_HID/128)

// -------- scratch (device globals; no allocation allowed) --------
__device__ float               g_partial[(size_t)M_CAND * NTILES];  // per n-tile score partials
__device__ float               g_scores[M_CAND];
__device__ unsigned long long  g_keys[SORT_N];
__device__ int                 g_sel[NTOP];

// ============================================================
// 1) Fused: h = relu(A@W1 + b1); partial_score = h_tile . W2_tile
//    fp32 SIMT GEMM, 128x128x8 tile, 8x8 micro-tile, 256 threads
// ============================================================
__global__ void __launch_bounds__(256, 2)
gemm_fused_kernel(const float* __restrict__ A,
                  const float* __restrict__ B,
                  const float* __restrict__ b1,
                  const float* __restrict__ W2) {
    __shared__ float As[8][128];
    __shared__ float Bs[8][128];
    __shared__ float sred[128][17];   // padded: conflict-free column reduce

    const int bm = blockIdx.y * 128;
    const int bn = blockIdx.x * 128;
    const int tid = threadIdx.x;
    const int tm = tid >> 4, tn = tid & 15;

    // loaders
    const int a_row = tid >> 1, a_col = (tid & 1) << 2;   // 128 rows x 8 cols
    const int b_row = tid >> 5, b_col = (tid & 31) << 2;  // 8 rows x 128 cols
    const int gr = bm + a_row;
    const int gc = bn + b_col;

    float acc[8][8];
#pragma unroll
    for (int i = 0; i < 8; i++)
#pragma unroll
        for (int j = 0; j < 8; j++) acc[i][j] = 0.f;

    for (int k0 = 0; k0 < K_DIM; k0 += 8) {
        float4 av = make_float4(0.f, 0.f, 0.f, 0.f);
        if (gr < M_CAND)
            av = *reinterpret_cast<const float4*>(&A[(size_t)gr * K_DIM + k0 + a_col]);
        As[a_col + 0][a_row] = av.x;
        As[a_col + 1][a_row] = av.y;
        As[a_col + 2][a_row] = av.z;
        As[a_col + 3][a_row] = av.w;

        const float* brp = &B[(size_t)(k0 + b_row) * N_HID];
        float4 bv = make_float4(0.f, 0.f, 0.f, 0.f);
        if (gc + 3 < N_HID) {
            bv = *reinterpret_cast<const float4*>(&brp[gc]);
        } else {
            if (gc + 0 < N_HID) bv.x = brp[gc + 0];
            if (gc + 1 < N_HID) bv.y = brp[gc + 1];
            if (gc + 2 < N_HID) bv.z = brp[gc + 2];
        }
        Bs[b_row][b_col + 0] = bv.x;
        Bs[b_row][b_col + 1] = bv.y;
        Bs[b_row][b_col + 2] = bv.z;
        Bs[b_row][b_col + 3] = bv.w;
        __syncthreads();

#pragma unroll
        for (int k = 0; k < 8; k++) {
            float4 ra0 = *reinterpret_cast<const float4*>(&As[k][tm * 8]);
            float4 ra1 = *reinterpret_cast<const float4*>(&As[k][tm * 8 + 4]);
            float4 rb0 = *reinterpret_cast<const float4*>(&Bs[k][tn * 8]);
            float4 rb1 = *reinterpret_cast<const float4*>(&Bs[k][tn * 8 + 4]);
            float ra[8] = {ra0.x, ra0.y, ra0.z, ra0.w, ra1.x, ra1.y, ra1.z, ra1.w};
            float rb[8] = {rb0.x, rb0.y, rb0.z, rb0.w, rb1.x, rb1.y, rb1.z, rb1.w};
#pragma unroll
            for (int i = 0; i < 8; i++)
#pragma unroll
                for (int j = 0; j < 8; j++)
                    acc[i][j] = fmaf(ra[i], rb[j], acc[i][j]);
        }
        __syncthreads();
    }

    // Fused epilogue: relu(acc + b1) dot W2 per row (j ascending = deterministic)
    float rowsum[8];
#pragma unroll
    for (int i = 0; i < 8; i++) rowsum[i] = 0.f;
#pragma unroll
    for (int j = 0; j < 8; j++) {
        int col = bn + tn * 8 + j;
        if (col < N_HID) {
            float w = W2[col];
            float bb = b1[col];
#pragma unroll
            for (int i = 0; i < 8; i++) {
                float v = acc[i][j] + bb;
                v = v > 0.f ? v : 0.f;
                rowsum[i] = fmaf(v, w, rowsum[i]);
            }
        }
    }
#pragma unroll
    for (int i = 0; i < 8; i++) sred[tm * 8 + i][tn] = rowsum[i];
    __syncthreads();

    if (tid < 128) {
        float s = 0.f;
#pragma unroll
        for (int t = 0; t < 16; t++) s += sred[tid][t];   // tn ascending: deterministic
        int r = bm + tid;
        if (r < M_CAND) g_partial[(size_t)r * NTILES + blockIdx.x] = s;
    }
}

// ============================================================
// 2) scores[i] = sum_t partial[i][t] + b2  (fixed order)
// ============================================================
__global__ void reduce_scores_kernel(const float* __restrict__ b2) {
    int i = blockIdx.x * blockDim.x + threadIdx.x;
    if (i < M_CAND) {
        float s = 0.f;
#pragma unroll
        for (int t = 0; t < NTILES; t++) s += g_partial[(size_t)i * NTILES + t];
        g_scores[i] = s + b2[0];
    }
}

// ============================================================
// 3) sort keys: (descending score bits << 32) | idx  -> ascending u64 sort
//    reproduces stable jnp.argsort(-scores)
// ============================================================
__global__ void build_keys_kernel() {
    int i = blockIdx.x * blockDim.x + threadIdx.x;
    if (i >= SORT_N) return;
    if (i < M_CAND) {
        unsigned u = __float_as_uint(g_scores[i]);
        unsigned m = (u & 0x80000000u) ? ~u : (u | 0x80000000u); // ascending-monotonic
        unsigned d = ~m;                                         // descending
        g_keys[i] = (((unsigned long long)d) << 32) | (unsigned)i;
    } else {
        g_keys[i] = ~0ull; // pads to the end
    }
}

__device__ __forceinline__ void cmpswap(unsigned long long& a, unsigned long long& b, bool up) {
    if ((a > b) == up) { unsigned long long t = a; a = b; b = t; }
}

// full bitonic sort of each 4096-element segment
__global__ void bitonic_local_sort() {
    __shared__ unsigned long long s[4096];
    const int base = blockIdx.x * 4096;
    for (int i = threadIdx.x; i < 4096; i += blockDim.x) s[i] = g_keys[base + i];
    __syncthreads();
    for (int k = 2; k <= 4096; k <<= 1) {
        for (int j = k >> 1; j > 0; j >>= 1) {
            for (int i = threadIdx.x; i < 4096; i += blockDim.x) {
                int l = i ^ j;
                if (l > i) {
                    bool up = (((base + i) & k) == 0);
                    unsigned long long a = s[i], b = s[l];
                    cmpswap(a, b, up);
                    s[i] = a; s[l] = b;
                }
            }
            __syncthreads();
        }
    }
    for (int i = threadIdx.x; i < 4096; i += blockDim.x) g_keys[base + i] = s[i];
}

__global__ void bitonic_global_step(int k, int j) {
    int i = blockIdx.x * blockDim.x + threadIdx.x;
    if (i >= SORT_N) return;
    int l = i ^ j;
    if (l > i) {
        unsigned long long a = g_keys[i], b = g_keys[l];
        bool up = ((i & k) == 0);
        if ((a > b) == up) { g_keys[i] = b; g_keys[l] = a; }
    }
}

// finish a merge for stride j = 2048..1 inside each 4096 segment
__global__ void bitonic_local_merge(int k) {
    __shared__ unsigned long long s[4096];
    const int base = blockIdx.x * 4096;
    for (int i = threadIdx.x; i < 4096; i += blockDim.x) s[i] = g_keys[base + i];
    __syncthreads();
    for (int j = 2048; j > 0; j >>= 1) {
        for (int i = threadIdx.x; i < 4096; i += blockDim.x) {
            int l = i ^ j;
            if (l > i) {
                bool up = (((base + i) & k) == 0);
                unsigned long long a = s[i], b = s[l];
                cmpswap(a, b, up);
                s[i] = a; s[l] = b;
            }
        }
        __syncthreads();
    }
    for (int i = threadIdx.x; i < 4096; i += blockDim.x) g_keys[base + i] = s[i];
}

// ============================================================
// 4) greedy non-crossing span extraction (warp-serial, early exit)
//    then stable sort accepted by (start*NW+end, accept order)
// ============================================================
__global__ void extract_kernel(const int* __restrict__ starts,
                               const int* __restrict__ ends,
                               const int* __restrict__ ntop_ptr) {
    __shared__ short stme[NUM_WORDS];          // start -> max end
    __shared__ short etms[NUM_WORDS];          // end   -> min start
    __shared__ unsigned long long acc[2048];   // packed (key<<27 | seq<<16 | cand)
    __shared__ int sh_count;
    const int tid = threadIdx.x;

    for (int i = tid; i < NUM_WORDS; i += blockDim.x) { stme[i] = -1; etms[i] = -1; }
    for (int i = tid; i < 2048; i += blockDim.x) acc[i] = ~0ull;
    __syncthreads();

    if (tid < 32) {
        const int lane = tid;
        int ntop = NTOP;
        if (ntop_ptr) { int v = *ntop_ptr; ntop = v < NTOP ? v : NTOP; }
        int count = 0;
        for (int i = 0; i < M_CAND && count < ntop; i++) {
            unsigned long long kv = g_keys[i];
            int cand = (int)(unsigned)(kv & 0xFFFFFFFFull);
            int s = starts[cand], e = ends[cand];
            bool c = false;
            if (lane <= MAXW) {
                int pos = s + lane;
                if (pos <= e) {
                    int me = (int)stme[pos];
                    int ms = (int)etms[pos];
                    c = ((pos > s) && (me > e)) || ((pos < e) && (ms >= 0) && (ms < s));
                }
            }
            unsigned b = __ballot_sync(0xffffffffu, c);
            if (b == 0u) {
                if (lane == 0) {
                    if (e > (int)stme[s]) stme[s] = (short)e;
                    int t = (int)etms[e];
                    if (t == -1 || s < t) etms[e] = (short)s;
                    acc[count] = (((unsigned long long)(s * NUM_WORDS + e)) << 27)
                               | (((unsigned long long)count) << 16)
                               | (unsigned long long)(unsigned)cand;
                }
                count++;
            }
            __syncwarp();
        }
        if (lane == 0) sh_count = count;
    }
    __syncthreads();

    // bitonic sort acc[2048] ascending (stable via embedded seq)
    for (int k = 2; k <= 2048; k <<= 1) {
        for (int j = k >> 1; j > 0; j >>= 1) {
            for (int i = tid; i < 2048; i += blockDim.x) {
                int l = i ^ j;
                if (l > i) {
                    bool up = ((i & k) == 0);
                    unsigned long long a = acc[i], b = acc[l];
                    cmpswap(a, b, up);
                    acc[i] = a; acc[l] = b;
                }
            }
            __syncthreads();
        }
    }
    const int cnt = sh_count;
    for (int i = tid; i < NTOP; i += blockDim.x) {
        unsigned long long v = (i < cnt) ? acc[i] : acc[0];
        g_sel[i] = (int)(v & 0xFFFFull);
    }
}

// ============================================================
// 5) gather outputs: [idx(float) | scores | emb rows]
// ============================================================
__global__ void gather_kernel(const float* __restrict__ emb, float* __restrict__ out,
                              int full_layout) {
    const int b = blockIdx.x;          // 0..NTOP-1
    const int sel = g_sel[b];
    float* oemb = out + (full_layout ? 2 * NTOP : 0);
    if (full_layout && threadIdx.x == 0) {
        out[b]        = (float)sel;
        out[NTOP + b] = g_scores[sel];
    }
    const float4* src = reinterpret_cast<const float4*>(&emb[(size_t)sel * K_DIM]);
    float4* dst       = reinterpret_cast<float4*>(&oemb[(size_t)b * K_DIM]);
    for (int j = threadIdx.x; j < K_DIM / 4; j += blockDim.x) dst[j] = src[j];
}

// ============================================================
extern "C" void kernel_launch(void* const* d_in, const int* in_sizes, int n_in,
                              void* d_out, int out_size) {
    const float* span_emb = (const float*)d_in[0];
    const float* W1       = (const float*)d_in[1];
    const float* b1       = (const float*)d_in[2];
    const float* W2       = (const float*)d_in[3];
    const float* b2       = (const float*)d_in[4];
    const int*   starts   = (const int*)d_in[5];
    const int*   ends     = (const int*)d_in[6];
    const int*   ntop     = (n_in > 7) ? (const int*)d_in[7] : nullptr;

    // 1) fused GEMM + bias + relu + score partials
    dim3 grid(NTILES, (M_CAND + 127) / 128);
    gemm_fused_kernel<<<grid, 256>>>(span_emb, W1, b1, W2);

    // 2) score reduce
    reduce_scores_kernel<<<(M_CAND + 255) / 256, 256>>>(b2);

    // 3) sort
    build_keys_kernel<<<SORT_N / 256, 256>>>();
    bitonic_local_sort<<<16, 1024>>>();
    for (int k = 8192; k <= SORT_N; k <<= 1) {
        for (int j = k >> 1; j >= 4096; j >>= 1)
            bitonic_global_step<<<SORT_N / 256, 256>>>(k, j);
        bitonic_local_merge<<<16, 1024>>>(k);
    }

    // 4) extraction
    extract_kernel<<<1, 1024>>>(starts, ends, ntop);

    // 5) gather
    const long long full_sz = (long long)2 * NTOP + (long long)NTOP * K_DIM;
    int full_layout = (out_size == (int)full_sz) ? 1 : (out_size == NTOP * K_DIM ? 0 : 1);
    gather_kernel<<<NTOP, 256>>>(span_emb, (float*)d_out, full_layout);
}

// round 5
// speedup vs baseline: 1.0027x; 1.0027x over previous
#include <cuda_runtime.h>
#include <cstdint>

// Problem constants (fixed by reference)
#define M_CAND    50000
#define K_DIM     2304
#define N_HID     1000
#define NUM_WORDS 5000
#define NTOP      2000
#define MAXW      10
#define SORT_N    65536
#define NTILES    8        // ceil(N_HID/128)

// -------- scratch (device globals; no allocation allowed) --------
__device__ float               g_partial[(size_t)M_CAND * NTILES];  // per n-tile score partials
__device__ float               g_scores[M_CAND];
__device__ unsigned long long  g_keys[SORT_N];
__device__ int                 g_sel[NTOP];

// ============================================================
// 1) Fused: h = relu(A@W1 + b1); partial_score = h_tile . W2_tile
//    fp32 SIMT GEMM, 128x128x8 tile, 8x8 micro-tile, 256 threads
// ============================================================
__global__ void __launch_bounds__(256, 2)
gemm_fused_kernel(const float* __restrict__ A,
                  const float* __restrict__ B,
                  const float* __restrict__ b1,
                  const float* __restrict__ W2) {
    __shared__ float As[8][128];
    __shared__ float Bs[8][128];
    __shared__ float sred[128][17];   // padded: conflict-free column reduce

    const int bm = blockIdx.y * 128;
    const int bn = blockIdx.x * 128;
    const int tid = threadIdx.x;
    const int tm = tid >> 4, tn = tid & 15;

    // loaders
    const int a_row = tid >> 1, a_col = (tid & 1) << 2;   // 128 rows x 8 cols
    const int b_row = tid >> 5, b_col = (tid & 31) << 2;  // 8 rows x 128 cols
    const int gr = bm + a_row;
    const int gc = bn + b_col;

    float acc[8][8];
#pragma unroll
    for (int i = 0; i < 8; i++)
#pragma unroll
        for (int j = 0; j < 8; j++) acc[i][j] = 0.f;

    for (int k0 = 0; k0 < K_DIM; k0 += 8) {
        float4 av = make_float4(0.f, 0.f, 0.f, 0.f);
        if (gr < M_CAND)
            av = *reinterpret_cast<const float4*>(&A[(size_t)gr * K_DIM + k0 + a_col]);
        As[a_col + 0][a_row] = av.x;
        As[a_col + 1][a_row] = av.y;
        As[a_col + 2][a_row] = av.z;
        As[a_col + 3][a_row] = av.w;

        const float* brp = &B[(size_t)(k0 + b_row) * N_HID];
        float4 bv = make_float4(0.f, 0.f, 0.f, 0.f);
        if (gc + 3 < N_HID) {
            bv = *reinterpret_cast<const float4*>(&brp[gc]);
        } else {
            if (gc + 0 < N_HID) bv.x = brp[gc + 0];
            if (gc + 1 < N_HID) bv.y = brp[gc + 1];
            if (gc + 2 < N_HID) bv.z = brp[gc + 2];
        }
        Bs[b_row][b_col + 0] = bv.x;
        Bs[b_row][b_col + 1] = bv.y;
        Bs[b_row][b_col + 2] = bv.z;
        Bs[b_row][b_col + 3] = bv.w;
        __syncthreads();

#pragma unroll
        for (int k = 0; k < 8; k++) {
            float4 ra0 = *reinterpret_cast<const float4*>(&As[k][tm * 8]);
            float4 ra1 = *reinterpret_cast<const float4*>(&As[k][tm * 8 + 4]);
            float4 rb0 = *reinterpret_cast<const float4*>(&Bs[k][tn * 8]);
            float4 rb1 = *reinterpret_cast<const float4*>(&Bs[k][tn * 8 + 4]);
            float ra[8] = {ra0.x, ra0.y, ra0.z, ra0.w, ra1.x, ra1.y, ra1.z, ra1.w};
            float rb[8] = {rb0.x, rb0.y, rb0.z, rb0.w, rb1.x, rb1.y, rb1.z, rb1.w};
#pragma unroll
            for (int i = 0; i < 8; i++)
#pragma unroll
                for (int j = 0; j < 8; j++)
                    acc[i][j] = fmaf(ra[i], rb[j], acc[i][j]);
        }
        __syncthreads();
    }

    // Fused epilogue: relu(acc + b1) dot W2 per row (j ascending = deterministic)
    float rowsum[8];
#pragma unroll
    for (int i = 0; i < 8; i++) rowsum[i] = 0.f;
#pragma unroll
    for (int j = 0; j < 8; j++) {
        int col = bn + tn * 8 + j;
        if (col < N_HID) {
            float w = W2[col];
            float bb = b1[col];
#pragma unroll
            for (int i = 0; i < 8; i++) {
                float v = acc[i][j] + bb;
                v = v > 0.f ? v : 0.f;
                rowsum[i] = fmaf(v, w, rowsum[i]);
            }
        }
    }
#pragma unroll
    for (int i = 0; i < 8; i++) sred[tm * 8 + i][tn] = rowsum[i];
    __syncthreads();

    if (tid < 128) {
        float s = 0.f;
#pragma unroll
        for (int t = 0; t < 16; t++) s += sred[tid][t];   // tn ascending: deterministic
        int r = bm + tid;
        if (r < M_CAND) g_partial[(size_t)r * NTILES + blockIdx.x] = s;
    }
}

// ============================================================
// 2) scores[i] = sum_t partial[i][t] + b2  (fixed order)
// ============================================================
__global__ void reduce_scores_kernel(const float* __restrict__ b2) {
    int i = blockIdx.x * blockDim.x + threadIdx.x;
    if (i < M_CAND) {
        float s = 0.f;
#pragma unroll
        for (int t = 0; t < NTILES; t++) s += g_partial[(size_t)i * NTILES + t];
        g_scores[i] = s + b2[0];
    }
}

// ============================================================
// 3) sort keys: (descending score bits << 32) | idx  -> ascending u64 sort
//    reproduces stable jnp.argsort(-scores)
// ============================================================
__global__ void build_keys_kernel() {
    int i = blockIdx.x * blockDim.x + threadIdx.x;
    if (i >= SORT_N) return;
    if (i < M_CAND) {
        unsigned u = __float_as_uint(g_scores[i]);
        unsigned m = (u & 0x80000000u) ? ~u : (u | 0x80000000u); // ascending-monotonic
        unsigned d = ~m;                                         // descending
        g_keys[i] = (((unsigned long long)d) << 32) | (unsigned)i;
    } else {
        g_keys[i] = ~0ull; // pads to the end
    }
}

__device__ __forceinline__ void cmpswap(unsigned long long& a, unsigned long long& b, bool up) {
    if ((a > b) == up) { unsigned long long t = a; a = b; b = t; }
}

// full bitonic sort of each 4096-element segment
__global__ void bitonic_local_sort() {
    __shared__ unsigned long long s[4096];
    const int base = blockIdx.x * 4096;
    for (int i = threadIdx.x; i < 4096; i += blockDim.x) s[i] = g_keys[base + i];
    __syncthreads();
    for (int k = 2; k <= 4096; k <<= 1) {
        for (int j = k >> 1; j > 0; j >>= 1) {
            for (int i = threadIdx.x; i < 4096; i += blockDim.x) {
                int l = i ^ j;
                if (l > i) {
                    bool up = (((base + i) & k) == 0);
                    unsigned long long a = s[i], b = s[l];
                    cmpswap(a, b, up);
                    s[i] = a; s[l] = b;
                }
            }
            __syncthreads();
        }
    }
    for (int i = threadIdx.x; i < 4096; i += blockDim.x) g_keys[base + i] = s[i];
}

__global__ void bitonic_global_step(int k, int j) {
    int i = blockIdx.x * blockDim.x + threadIdx.x;
    if (i >= SORT_N) return;
    int l = i ^ j;
    if (l > i) {
        unsigned long long a = g_keys[i], b = g_keys[l];
        bool up = ((i & k) == 0);
        if ((a > b) == up) { g_keys[i] = b; g_keys[l] = a; }
    }
}

// finish a merge for stride j = 2048..1 inside each 4096 segment
__global__ void bitonic_local_merge(int k) {
    __shared__ unsigned long long s[4096];
    const int base = blockIdx.x * 4096;
    for (int i = threadIdx.x; i < 4096; i += blockDim.x) s[i] = g_keys[base + i];
    __syncthreads();
    for (int j = 2048; j > 0; j >>= 1) {
        for (int i = threadIdx.x; i < 4096; i += blockDim.x) {
            int l = i ^ j;
            if (l > i) {
                bool up = (((base + i) & k) == 0);
                unsigned long long a = s[i], b = s[l];
                cmpswap(a, b, up);
                s[i] = a; s[l] = b;
            }
        }
        __syncthreads();
    }
    for (int i = threadIdx.x; i < 4096; i += blockDim.x) g_keys[base + i] = s[i];
}

// ============================================================
// 4) greedy non-crossing span extraction (warp-serial, early exit)
//    then stable sort accepted by (start*NW+end, accept order)
// ============================================================
__global__ void extract_kernel(const int* __restrict__ starts,
                               const int* __restrict__ ends,
                               const int* __restrict__ ntop_ptr) {
    __shared__ short stme[NUM_WORDS];          // start -> max end
    __shared__ short etms[NUM_WORDS];          // end   -> min start
    __shared__ unsigned long long acc[2048];   // packed (key<<27 | seq<<16 | cand)
    __shared__ int sh_count;
    const int tid = threadIdx.x;

    for (int i = tid; i < NUM_WORDS; i += blockDim.x) { stme[i] = -1; etms[i] = -1; }
    for (int i = tid; i < 2048; i += blockDim.x) acc[i] = ~0ull;
    __syncthreads();

    if (tid < 32) {
        const int lane = tid;
        int ntop = NTOP;
        if (ntop_ptr) { int v = *ntop_ptr; ntop = v < NTOP ? v : NTOP; }
        int count = 0;
        for (int i = 0; i < M_CAND && count < ntop; i++) {
            unsigned long long kv = g_keys[i];
            int cand = (int)(unsigned)(kv & 0xFFFFFFFFull);
            int s = starts[cand], e = ends[cand];
            bool c = false;
            if (lane <= MAXW) {
                int pos = s + lane;
                if (pos <= e) {
                    int me = (int)stme[pos];
                    int ms = (int)etms[pos];
                    c = ((pos > s) && (me > e)) || ((pos < e) && (ms >= 0) && (ms < s));
                }
            }
            unsigned b = __ballot_sync(0xffffffffu, c);
            if (b == 0u) {
                if (lane == 0) {
                    if (e > (int)stme[s]) stme[s] = (short)e;
                    int t = (int)etms[e];
                    if (t == -1 || s < t) etms[e] = (short)s;
                    acc[count] = (((unsigned long long)(s * NUM_WORDS + e)) << 27)
                               | (((unsigned long long)count) << 16)
                               | (unsigned long long)(unsigned)cand;
                }
                count++;
            }
            __syncwarp();
        }
        if (lane == 0) sh_count = count;
    }
    __syncthreads();

    // bitonic sort acc[2048] ascending (stable via embedded seq)
    for (int k = 2; k <= 2048; k <<= 1) {
        for (int j = k >> 1; j > 0; j >>= 1) {
            for (int i = tid; i < 2048; i += blockDim.x) {
                int l = i ^ j;
                if (l > i) {
                    bool up = ((i & k) == 0);
                    unsigned long long a = acc[i], b = acc[l];
                    cmpswap(a, b, up);
                    acc[i] = a; acc[l] = b;
                }
            }
            __syncthreads();
        }
    }
    const int cnt = sh_count;
    for (int i = tid; i < NTOP; i += blockDim.x) {
        unsigned long long v = (i < cnt) ? acc[i] : acc[0];
        g_sel[i] = (int)(v & 0xFFFFull);
    }
}

// ============================================================
// 5) gather outputs: [idx(float) | scores | emb rows]
// ============================================================
__global__ void gather_kernel(const float* __restrict__ emb, float* __restrict__ out,
                              int full_layout) {
    const int b = blockIdx.x;          // 0..NTOP-1
    const int sel = g_sel[b];
    float* oemb = out + (full_layout ? 2 * NTOP : 0);
    if (full_layout && threadIdx.x == 0) {
        out[b]        = (float)sel;
        out[NTOP + b] = g_scores[sel];
    }
    const float4* src = reinterpret_cast<const float4*>(&emb[(size_t)sel * K_DIM]);
    float4* dst       = reinterpret_cast<float4*>(&oemb[(size_t)b * K_DIM]);
    for (int j = threadIdx.x; j < K_DIM / 4; j += blockDim.x) dst[j] = src[j];
}

// ============================================================
extern "C" void kernel_launch(void* const* d_in, const int* in_sizes, int n_in,
                              void* d_out, int out_size) {
    const float* span_emb = (const float*)d_in[0];
    const float* W1       = (const float*)d_in[1];
    const float* b1       = (const float*)d_in[2];
    const float* W2       = (const float*)d_in[3];
    const float* b2       = (const float*)d_in[4];
    const int*   starts   = (const int*)d_in[5];
    const int*   ends     = (const int*)d_in[6];
    const int*   ntop     = (n_in > 7) ? (const int*)d_in[7] : nullptr;

    // 1) fused GEMM + bias + relu + score partials
    dim3 grid(NTILES, (M_CAND + 127) / 128);
    gemm_fused_kernel<<<grid, 256>>>(span_emb, W1, b1, W2);

    // 2) score reduce
    reduce_scores_kernel<<<(M_CAND + 255) / 256, 256>>>(b2);

    // 3) sort
    build_keys_kernel<<<SORT_N / 256, 256>>>();
    bitonic_local_sort<<<16, 1024>>>();
    for (int k = 8192; k <= SORT_N; k <<= 1) {
        for (int j = k >> 1; j >= 4096; j >>= 1)
            bitonic_global_step<<<SORT_N / 256, 256>>>(k, j);
        bitonic_local_merge<<<16, 1024>>>(k);
    }

    // 4) extraction
    extract_kernel<<<1, 1024>>>(starts, ends, ntop);

    // 5) gather
    const long long full_sz = (long long)2 * NTOP + (long long)NTOP * K_DIM;
    int full_layout = (out_size == (int)full_sz) ? 1 : (out_size == NTOP * K_DIM ? 0 : 1);
    gather_kernel<<<NTOP, 256>>>(span_emb, (float*)d_out, full_layout);
}

// round 7
// speedup vs baseline: 1.1872x; 1.1840x over previous
#include <cuda_runtime.h>
#include <cstdint>

// Problem constants (fixed by reference)
#define M_CAND    50000
#define K_DIM     2304
#define N_HID     1000
#define NUM_WORDS 5000
#define NTOP      2000
#define MAXW      10
#define SORT_N    65536
#define NTILES    8        // ceil(N_HID/128)

// -------- scratch (device globals; no allocation allowed) --------
__device__ float               g_partial[(size_t)M_CAND * NTILES];
__device__ float               g_scores[M_CAND];
__device__ unsigned long long  g_keys[SORT_N];
__device__ int                 g_sel[NTOP];

// ---- packed f32x2 helpers (Blackwell: 2x fp32 FMA throughput, IEEE-exact) ----
__device__ __forceinline__ unsigned long long pk2(float x, float y) {
    unsigned long long r;
    asm("mov.b64 %0, {%1, %2};" : "=l"(r) : "f"(x), "f"(y));
    return r;
}
__device__ __forceinline__ void upk2(unsigned long long v, float& x, float& y) {
    asm("mov.b64 {%0, %1}, %2;" : "=f"(x), "=f"(y) : "l"(v));
}
__device__ __forceinline__ unsigned long long ffma2(unsigned long long a,
                                                    unsigned long long b,
                                                    unsigned long long c) {
    unsigned long long d;
    asm("fma.rn.f32x2 %0, %1, %2, %3;" : "=l"(d) : "l"(a), "l"(b), "l"(c));
    return d;
}

// ============================================================
// 1) Fused: h = relu(A@W1 + b1); partial_score = h_tile . W2_tile
//    fp32 SIMT GEMM via packed f32x2 FMA, 128x128x8 tile, 256 thr
// ============================================================
__global__ void __launch_bounds__(256, 2)
gemm_fused_kernel(const float* __restrict__ A,
                  const float* __restrict__ B,
                  const float* __restrict__ b1,
                  const float* __restrict__ W2) {
    __shared__ float As[8][128];
    __shared__ float Bs[8][128];
    __shared__ float sred[128][17];   // padded: conflict-free column reduce

    const int bm = blockIdx.y * 128;
    const int bn = blockIdx.x * 128;
    const int tid = threadIdx.x;
    const int tm = tid >> 4, tn = tid & 15;

    // loaders
    const int a_row = tid >> 1, a_col = (tid & 1) << 2;   // 128 rows x 8 cols
    const int b_row = tid >> 5, b_col = (tid & 31) << 2;  // 8 rows x 128 cols
    const int gr = bm + a_row;
    const int gc = bn + b_col;

    // acc2[i][jp] holds (j=2jp, j=2jp+1) as packed f32x2
    unsigned long long acc2[8][4];
#pragma unroll
    for (int i = 0; i < 8; i++)
#pragma unroll
        for (int jp = 0; jp < 4; jp++) acc2[i][jp] = 0ull;

    for (int k0 = 0; k0 < K_DIM; k0 += 8) {
        float4 av = make_float4(0.f, 0.f, 0.f, 0.f);
        if (gr < M_CAND)
            av = *reinterpret_cast<const float4*>(&A[(size_t)gr * K_DIM + k0 + a_col]);
        As[a_col + 0][a_row] = av.x;
        As[a_col + 1][a_row] = av.y;
        As[a_col + 2][a_row] = av.z;
        As[a_col + 3][a_row] = av.w;

        const float* brp = &B[(size_t)(k0 + b_row) * N_HID];
        float4 bv = make_float4(0.f, 0.f, 0.f, 0.f);
        if (gc + 3 < N_HID) {
            bv = *reinterpret_cast<const float4*>(&brp[gc]);
        } else {
            if (gc + 0 < N_HID) bv.x = brp[gc + 0];
            if (gc + 1 < N_HID) bv.y = brp[gc + 1];
            if (gc + 2 < N_HID) bv.z = brp[gc + 2];
        }
        Bs[b_row][b_col + 0] = bv.x;
        Bs[b_row][b_col + 1] = bv.y;
        Bs[b_row][b_col + 2] = bv.z;
        Bs[b_row][b_col + 3] = bv.w;
        __syncthreads();

#pragma unroll
        for (int k = 0; k < 8; k++) {
            float4 ra0 = *reinterpret_cast<const float4*>(&As[k][tm * 8]);
            float4 ra1 = *reinterpret_cast<const float4*>(&As[k][tm * 8 + 4]);
            // B pairs straight from shared as packed 64-bit lanes (LDS.128)
            ulonglong2 rbA = *reinterpret_cast<const ulonglong2*>(&Bs[k][tn * 8]);
            ulonglong2 rbB = *reinterpret_cast<const ulonglong2*>(&Bs[k][tn * 8 + 4]);
            unsigned long long rb2[4] = {rbA.x, rbA.y, rbB.x, rbB.y};
            float ra[8] = {ra0.x, ra0.y, ra0.z, ra0.w, ra1.x, ra1.y, ra1.z, ra1.w};
#pragma unroll
            for (int i = 0; i < 8; i++) {
                unsigned long long aspl = pk2(ra[i], ra[i]);
#pragma unroll
                for (int jp = 0; jp < 4; jp++)
                    acc2[i][jp] = ffma2(aspl, rb2[jp], acc2[i][jp]);
            }
        }
        __syncthreads();
    }

    // Fused epilogue: relu(acc + b1) dot W2 per row (j ascending = deterministic,
    // bitwise identical to scalar version)
    float rowsum[8];
#pragma unroll
    for (int i = 0; i < 8; i++) rowsum[i] = 0.f;
#pragma unroll
    for (int jp = 0; jp < 4; jp++) {
#pragma unroll
        for (int h = 0; h < 2; h++) {
            int j = 2 * jp + h;
            int col = bn + tn * 8 + j;
            if (col < N_HID) {
                float w = W2[col];
                float bb = b1[col];
#pragma unroll
                for (int i = 0; i < 8; i++) {
                    float v0, v1;
                    upk2(acc2[i][jp], v0, v1);
                    float v = (h == 0 ? v0 : v1) + bb;
                    v = v > 0.f ? v : 0.f;
                    rowsum[i] = fmaf(v, w, rowsum[i]);
                }
            }
        }
    }
#pragma unroll
    for (int i = 0; i < 8; i++) sred[tm * 8 + i][tn] = rowsum[i];
    __syncthreads();

    if (tid < 128) {
        float s = 0.f;
#pragma unroll
        for (int t = 0; t < 16; t++) s += sred[tid][t];   // tn ascending: deterministic
        int r = bm + tid;
        if (r < M_CAND) g_partial[(size_t)r * NTILES + blockIdx.x] = s;
    }
}

// ============================================================
// 2) scores[i] = sum_t partial[i][t] + b2  (fixed order)
// ============================================================
__global__ void reduce_scores_kernel(const float* __restrict__ b2) {
    int i = blockIdx.x * blockDim.x + threadIdx.x;
    if (i < M_CAND) {
        float s = 0.f;
#pragma unroll
        for (int t = 0; t < NTILES; t++) s += g_partial[(size_t)i * NTILES + t];
        g_scores[i] = s + b2[0];
    }
}

// ============================================================
// 3) sort keys: (descending score bits << 32) | idx  -> ascending u64 sort
// ============================================================
__global__ void build_keys_kernel() {
    int i = blockIdx.x * blockDim.x + threadIdx.x;
    if (i >= SORT_N) return;
    if (i < M_CAND) {
        unsigned u = __float_as_uint(g_scores[i]);
        unsigned m = (u & 0x80000000u) ? ~u : (u | 0x80000000u);
        unsigned d = ~m;
        g_keys[i] = (((unsigned long long)d) << 32) | (unsigned)i;
    } else {
        g_keys[i] = ~0ull;
    }
}

__device__ __forceinline__ void cmpswap(unsigned long long& a, unsigned long long& b, bool up) {
    if ((a > b) == up) { unsigned long long t = a; a = b; b = t; }
}

__global__ void bitonic_local_sort() {
    __shared__ unsigned long long s[4096];
    const int base = blockIdx.x * 4096;
    for (int i = threadIdx.x; i < 4096; i += blockDim.x) s[i] = g_keys[base + i];
    __syncthreads();
    for (int k = 2; k <= 4096; k <<= 1) {
        for (int j = k >> 1; j > 0; j >>= 1) {
            for (int i = threadIdx.x; i < 4096; i += blockDim.x) {
                int l = i ^ j;
                if (l > i) {
                    bool up = (((base + i) & k) == 0);
                    unsigned long long a = s[i], b = s[l];
                    cmpswap(a, b, up);
                    s[i] = a; s[l] = b;
                }
            }
            __syncthreads();
        }
    }
    for (int i = threadIdx.x; i < 4096; i += blockDim.x) g_keys[base + i] = s[i];
}

__global__ void bitonic_global_step(int k, int j) {
    int i = blockIdx.x * blockDim.x + threadIdx.x;
    if (i >= SORT_N) return;
    int l = i ^ j;
    if (l > i) {
        unsigned long long a = g_keys[i], b = g_keys[l];
        bool up = ((i & k) == 0);
        if ((a > b) == up) { g_keys[i] = b; g_keys[l] = a; }
    }
}

__global__ void bitonic_local_merge(int k) {
    __shared__ unsigned long long s[4096];
    const int base = blockIdx.x * 4096;
    for (int i = threadIdx.x; i < 4096; i += blockDim.x) s[i] = g_keys[base + i];
    __syncthreads();
    for (int j = 2048; j > 0; j >>= 1) {
        for (int i = threadIdx.x; i < 4096; i += blockDim.x) {
            int l = i ^ j;
            if (l > i) {
                bool up = (((base + i) & k) == 0);
                unsigned long long a = s[i], b = s[l];
                cmpswap(a, b, up);
                s[i] = a; s[l] = b;
            }
        }
        __syncthreads();
    }
    for (int i = threadIdx.x; i < 4096; i += blockDim.x) g_keys[base + i] = s[i];
}

// ============================================================
// 4) greedy extraction: batched shared-memory prefetch + warp-serial scan
// ============================================================
#define XB 1024   // candidates prefetched per batch

__global__ void extract_kernel(const int* __restrict__ starts,
                               const int* __restrict__ ends,
                               const int* __restrict__ ntop_ptr) {
    __shared__ short stme[NUM_WORDS];          // start -> max end
    __shared__ short etms[NUM_WORDS];          // end   -> min start
    __shared__ unsigned long long acc[2048];   // packed (key<<27 | seq<<16 | cand)
    __shared__ int   sh_count;
    __shared__ int   sh_done;
    __shared__ int   bc[XB];                   // batch: candidate idx
    __shared__ short bs[XB], be[XB];           // batch: start/end
    const int tid = threadIdx.x;

    for (int i = tid; i < NUM_WORDS; i += blockDim.x) { stme[i] = -1; etms[i] = -1; }
    for (int i = tid; i < 2048; i += blockDim.x) acc[i] = ~0ull;
    if (tid == 0) sh_done = 0;
    __syncthreads();

    int ntop = NTOP;
    if (ntop_ptr) { int v = *ntop_ptr; ntop = v < NTOP ? v : NTOP; }
    int count = 0;   // tracked identically by all lanes of warp 0

    for (int base = 0; base < M_CAND; base += XB) {
        if (sh_done) break;
        // cooperative prefetch of this batch (coalesced keys, parallel gathers)
        int i = base + tid;
        if (i < M_CAND) {
            unsigned long long kv = g_keys[i];
            int cand = (int)(unsigned)(kv & 0xFFFFFFFFull);
            bc[tid] = cand;
            bs[tid] = (short)starts[cand];
            be[tid] = (short)ends[cand];
        }
        __syncthreads();

        if (tid < 32) {
            const int lane = tid;
            int n = M_CAND - base; if (n > XB) n = XB;
            for (int t = 0; t < n && count < ntop; t++) {
                int s = (int)bs[t], e = (int)be[t];
                bool c = false;
                if (lane <= MAXW) {
                    int pos = s + lane;
                    if (pos <= e) {
                        int me = (int)stme[pos];
                        int ms = (int)etms[pos];
                        c = ((pos > s) && (me > e)) || ((pos < e) && (ms >= 0) && (ms < s));
                    }
                }
                unsigned b = __ballot_sync(0xffffffffu, c);
                if (b == 0u) {
                    if (lane == 0) {
                        if (e > (int)stme[s]) stme[s] = (short)e;
                        int tt = (int)etms[e];
                        if (tt == -1 || s < tt) etms[e] = (short)s;
                        acc[count] = (((unsigned long long)(s * NUM_WORDS + e)) << 27)
                                   | (((unsigned long long)count) << 16)
                                   | (unsigned long long)(unsigned)bc[t];
                    }
                    count++;
                }
                __syncwarp();
            }
            if (lane == 0 && count >= ntop) sh_done = 1;
        }
        __syncthreads();   // orders scan before next batch overwrite + sh_done visibility
    }

    if (tid == 0) sh_count = count;
    __syncthreads();

    // bitonic sort acc[2048] ascending (stable via embedded seq)
    for (int k = 2; k <= 2048; k <<= 1) {
        for (int j = k >> 1; j > 0; j >>= 1) {
            for (int i = tid; i < 2048; i += blockDim.x) {
                int l = i ^ j;
                if (l > i) {
                    bool up = ((i & k) == 0);
                    unsigned long long a = acc[i], b = acc[l];
                    cmpswap(a, b, up);
                    acc[i] = a; acc[l] = b;
                }
            }
            __syncthreads();
        }
    }
    const int cnt = sh_count;
    for (int i = tid; i < NTOP; i += blockDim.x) {
        unsigned long long v = (i < cnt) ? acc[i] : acc[0];
        g_sel[i] = (int)(v & 0xFFFFull);
    }
}

// ============================================================
// 5) gather outputs: [idx(float) | scores | emb rows]
// ============================================================
__global__ void gather_kernel(const float* __restrict__ emb, float* __restrict__ out,
                              int full_layout) {
    const int b = blockIdx.x;
    const int sel = g_sel[b];
    float* oemb = out + (full_layout ? 2 * NTOP : 0);
    if (full_layout && threadIdx.x == 0) {
        out[b]        = (float)sel;
        out[NTOP + b] = g_scores[sel];
    }
    const float4* src = reinterpret_cast<const float4*>(&emb[(size_t)sel * K_DIM]);
    float4* dst       = reinterpret_cast<float4*>(&oemb[(size_t)b * K_DIM]);
    for (int j = threadIdx.x; j < K_DIM / 4; j += blockDim.x) dst[j] = src[j];
}

// ============================================================
extern "C" void kernel_launch(void* const* d_in, const int* in_sizes, int n_in,
                              void* d_out, int out_size) {
    const float* span_emb = (const float*)d_in[0];
    const float* W1       = (const float*)d_in[1];
    const float* b1       = (const float*)d_in[2];
    const float* W2       = (const float*)d_in[3];
    const float* b2       = (const float*)d_in[4];
    const int*   starts   = (const int*)d_in[5];
    const int*   ends     = (const int*)d_in[6];
    const int*   ntop     = (n_in > 7) ? (const int*)d_in[7] : nullptr;

    // 1) fused GEMM + bias + relu + score partials (packed f32x2)
    dim3 grid(NTILES, (M_CAND + 127) / 128);
    gemm_fused_kernel<<<grid, 256>>>(span_emb, W1, b1, W2);

    // 2) score reduce
    reduce_scores_kernel<<<(M_CAND + 255) / 256, 256>>>(b2);

    // 3) sort
    build_keys_kernel<<<SORT_N / 256, 256>>>();
    bitonic_local_sort<<<16, 1024>>>();
    for (int k = 8192; k <= SORT_N; k <<= 1) {
        for (int j = k >> 1; j >= 4096; j >>= 1)
            bitonic_global_step<<<SORT_N / 256, 256>>>(k, j);
        bitonic_local_merge<<<16, 1024>>>(k);
    }

    // 4) extraction
    extract_kernel<<<1, 1024>>>(starts, ends, ntop);

    // 5) gather
    const long long full_sz = (long long)2 * NTOP + (long long)NTOP * K_DIM;
    int full_layout = (out_size == (int)full_sz) ? 1 : (out_size == NTOP * K_DIM ? 0 : 1);
    gather_kernel<<<NTOP, 256>>>(span_emb, (float*)d_out, full_layout);
}